// round 11
// baseline (speedup 1.0000x reference)
#include <cuda_runtime.h>

// Problem constants (match reference)
#define BOX   120
#define VOL   (BOX * BOX * BOX)       // 1,728,000
#define NTYPE 11
#define BATCH 4
#define BT    (BATCH * NTYPE)         // 44
#define MAXA  512
#define NNB   2

#define THREADS    512
#define YHALF      60                          // y-extent per CTA
#define PLANE_F    (YHALF * BOX)               // 7200 floats per half-plane
#define PLANE_F4   (PLANE_F / 4)               // 1800 float4
#define F4_PER_ROW (BOX / 4)                   // 30 float4 per z-row
#define KMAX       4                           // ceil(1800 / 512)
#define NBLOCKS    (BT * BOX * 2)              // 10560 CTAs

// ---------------------------------------------------------------------------
// num_atoms dtype sniff: values in [1,512]. If int64 (LE), 32-bit word 1 is
// the zero high half of element 0; if int32, word 1 is num_atoms[1] >= 1.
// ---------------------------------------------------------------------------
__device__ __forceinline__ int get_natoms(const int* __restrict__ p, int bt) {
    return (p[1] == 0) ? p[2 * bt] : p[bt];
}

__device__ __forceinline__ void stcs4(float4* addr, float4 v) {
    asm volatile("st.global.cs.v4.f32 [%0], {%1, %2, %3, %4};"
                 :: "l"(addr), "f"(v.x), "f"(v.y), "f"(v.z), "f"(v.w) : "memory");
}

// ---------------------------------------------------------------------------
// Fused kernel, store-duty-cycle optimized. One CTA of 512 threads per
// (bt, x, y-half). Single-shot atom scan; untouched rows stream zeros to gmem
// IMMEDIATELY (overlapping this CTA's own scatter); touched rows go through
// a smem plane and are stored after the scatter. Output written exactly once.
// ---------------------------------------------------------------------------
__global__ void __launch_bounds__(THREADS) fused_kernel(
    const float* __restrict__ coords,    // [BT, 3*MAXA]
    const int* __restrict__ num_atoms,   // [BT] int32 (or int64, sniffed)
    float* __restrict__ out)             // [BT, VOL]
{
    __shared__ float plane[PLANE_F];         // 28.8 KB
    __shared__ int   alist[MAXA];            // matched atom indices (2 KB)
    __shared__ int   acnt;
    __shared__ unsigned rowmask[2];          // touched-row bits (60 rows)

    const int b  = blockIdx.x;
    const int h  = b & 1;                    // y-half
    const int x  = (b >> 1) % BOX;
    const int bt = b / (BOX * 2);
    const int y0 = h * YHALF;
    const int tid = threadIdx.x;

    const int na = get_natoms(num_atoms, bt);
    const float* cbt = coords + (long long)bt * (3 * MAXA);

    if (tid == 0) { acnt = 0; rowmask[0] = 0u; rowmask[1] = 0u; }
    __syncthreads();

    // Phase 1 (single shot): thread `tid` tests atom `tid`.
    if (tid < na) {
        const float ax = cbt[3 * tid + 0];
        const float ay = cbt[3 * tid + 1];
        const int cx = (int)floorf(ax);
        const int cy = (int)floorf(ay);
        const int ddx = x - cx;
        if (ddx >= -NNB && ddx <= NNB && cy >= y0 - NNB && cy <= y0 + YHALF - 1 + NNB) {
            alist[atomicAdd(&acnt, 1)] = tid;
            const int rlo = max(cy - NNB - y0, 0);
            const int rhi = min(cy + NNB - y0, YHALF - 1);
            // Set bits [rlo, rhi] (at most 5 bits, may straddle the word split).
            for (int wdi = rlo >> 5; wdi <= (rhi >> 5); wdi++) {
                const int lo = max(rlo - wdi * 32, 0);
                const int hi = min(rhi - wdi * 32, 31);
                const unsigned bits = (hi - lo == 31) ? 0xFFFFFFFFu
                                    : (((1u << (hi - lo + 1)) - 1u) << lo);
                atomicOr(&rowmask[wdi], bits);
            }
        }
    }
    __syncthreads();

    const int cnt = acnt;
    float4* dst = (float4*)(out + (long long)bt * VOL + x * (BOX * BOX) + y0 * BOX);
    const float4 zero4 = make_float4(0.f, 0.f, 0.f, 0.f);
    float4* pl4 = (float4*)plane;

    if (cnt == 0) {
        // No atoms: stream zeros straight from registers.
        #pragma unroll
        for (int k = 0; k < KMAX; k++) {
            const int f4 = tid + k * THREADS;
            if (f4 < PLANE_F4) stcs4(dst + f4, zero4);
        }
        return;
    }

    const unsigned m0 = rowmask[0], m1 = rowmask[1];   // broadcast LDS, once

    // Phase 2: untouched rows -> stream zeros to gmem NOW (independent of the
    // scatter; every scatter-written row is marked touched). Touched rows ->
    // zero the smem plane.
    #pragma unroll
    for (int k = 0; k < KMAX; k++) {
        const int f4 = tid + k * THREADS;
        if (f4 < PLANE_F4) {
            const int r = f4 / F4_PER_ROW;
            const unsigned touched = ((r < 32) ? (m0 >> r) : (m1 >> (r - 32))) & 1u;
            if (touched) pl4[f4] = zero4;
            else         stcs4(dst + f4, zero4);
        }
    }
    __syncthreads();

    // Phase 3: scatter matched atoms into smem. Warp per atom; lane l < 25
    // owns cell (cy + l/5 - 2, cz + l%5 - 2). 16 warps -> usually 1 iteration.
    {
        const int wid  = tid >> 5;
        const int lane = tid & 31;
        const float fx = (float)x;
        for (int i = wid; i < cnt; i += THREADS / 32) {
            const int a = alist[i];
            const float ax = cbt[3 * a + 0];
            const float ay = cbt[3 * a + 1];
            const float az = cbt[3 * a + 2];
            if (lane < 25) {
                const int cy = (int)floorf(ay);
                const int cz = (int)floorf(az);
                const int iy = cy + lane / 5 - NNB;
                const int iz = cz + lane % 5 - NNB;
                if (iy >= y0 && iy < y0 + YHALF && (unsigned)iz < BOX) {
                    const float dx = fx - ax;
                    const float dy = (float)iy - ay;
                    const float dz = (float)iz - az;
                    const float v = __expf(-(dx * dx + dy * dy + dz * dz));
                    atomicAdd(&plane[(iy - y0) * BOX + iz], v);
                }
            }
        }
    }
    __syncthreads();

    // Phase 4: store the touched rows from smem.
    #pragma unroll
    for (int k = 0; k < KMAX; k++) {
        const int f4 = tid + k * THREADS;
        if (f4 < PLANE_F4) {
            const int r = f4 / F4_PER_ROW;
            const unsigned touched = ((r < 32) ? (m0 >> r) : (m1 >> (r - 32))) & 1u;
            if (touched) stcs4(dst + f4, pl4[f4]);
        }
    }
}

// ---------------------------------------------------------------------------
extern "C" void kernel_launch(void* const* d_in, const int* in_sizes, int n_in,
                              void* d_out, int out_size) {
    const float* coords    = (const float*)d_in[0];  // float32 [4,11,1536]
    const int*   num_atoms = (const int*)d_in[1];    // int32/int64 [4,11]
    float*       out       = (float*)d_out;          // float32 [4,11,120,120,120]

    fused_kernel<<<NBLOCKS, THREADS>>>(coords, num_atoms, out);
}

// round 12
// speedup vs baseline: 1.1334x; 1.1334x over previous
#include <cuda_runtime.h>
#include <cstdint>

// Problem constants (match reference)
#define BOX   120
#define VOL   (BOX * BOX * BOX)       // 1,728,000
#define NTYPE 11
#define BATCH 4
#define BT    (BATCH * NTYPE)         // 44
#define MAXA  512
#define NNB   2

#define THREADS    256
#define YHALF      60                          // y-extent per CTA
#define PLANE_F    (YHALF * BOX)               // 7200 floats per half-plane
#define PLANE_F4   (PLANE_F / 4)               // 1800 float4
#define PLANE_B    (PLANE_F * 4)               // 28800 bytes
#define NBLOCKS    (BT * BOX * 2)              // 10560 CTAs

// ---------------------------------------------------------------------------
// num_atoms dtype sniff: values in [1,512]. If int64 (LE), 32-bit word 1 is
// the zero high half of element 0; if int32, word 1 is num_atoms[1] >= 1.
// ---------------------------------------------------------------------------
__device__ __forceinline__ int get_natoms(const int* __restrict__ p, int bt) {
    return (p[1] == 0) ? p[2 * bt] : p[bt];
}

__device__ __forceinline__ uint32_t smem_u32(const void* p) {
    uint32_t a;
    asm("{ .reg .u64 t; cvta.to.shared.u64 t, %1; cvt.u32.u64 %0, t; }"
        : "=r"(a) : "l"(p));
    return a;
}

// ---------------------------------------------------------------------------
// Fused kernel, TMA-store epilogue. One CTA of 256 threads per
// (bt, x, y-half). Zeroes its 60x120 tile in smem, scatters the few matching
// atoms via shared atomics, then streams the tile to gmem with a single
// cp.async.bulk (1D TMA store): perfect 128B bursts, near-zero issue cost.
// Output written exactly once; no global atomics; no pre-zero pass.
// ---------------------------------------------------------------------------
__global__ void __launch_bounds__(THREADS) fused_kernel(
    const float* __restrict__ coords,    // [BT, 3*MAXA]
    const int* __restrict__ num_atoms,   // [BT] int32 (or int64, sniffed)
    float* __restrict__ out)             // [BT, VOL]
{
    __shared__ __align__(16) float plane[PLANE_F];   // 28.8 KB
    __shared__ int alist[MAXA];                      // matched atom indices
    __shared__ int acnt;

    const int b  = blockIdx.x;
    const int h  = b & 1;                    // y-half
    const int x  = (b >> 1) % BOX;
    const int bt = b / (BOX * 2);
    const int y0 = h * YHALF;
    const int tid = threadIdx.x;

    const int na = get_natoms(num_atoms, bt);
    const float* cbt = coords + (long long)bt * (3 * MAXA);

    if (tid == 0) acnt = 0;
    __syncthreads();

    // Phase 1: zero the smem tile AND scan atoms (independent work, one phase).
    float4* pl4 = (float4*)plane;
    const float4 zero4 = make_float4(0.f, 0.f, 0.f, 0.f);
    #pragma unroll
    for (int k = 0; k < 8; k++) {
        const int f4 = tid + k * THREADS;
        if (f4 < PLANE_F4) pl4[f4] = zero4;
    }
    for (int a = tid; a < na; a += THREADS) {
        const float ax = cbt[3 * a + 0];
        const float ay = cbt[3 * a + 1];
        const int cx = (int)floorf(ax);
        const int cy = (int)floorf(ay);
        const int ddx = x - cx;
        if (ddx >= -NNB && ddx <= NNB && cy >= y0 - NNB && cy <= y0 + YHALF - 1 + NNB) {
            alist[atomicAdd(&acnt, 1)] = a;
        }
    }
    __syncthreads();

    const int cnt = acnt;

    // Phase 2: scatter matched atoms into smem. Warp per atom; lane l < 25
    // owns cell (cy + l/5 - 2, cz + l%5 - 2).
    if (cnt > 0) {
        const int wid  = tid >> 5;
        const int lane = tid & 31;
        const float fx = (float)x;
        for (int i = wid; i < cnt; i += THREADS / 32) {
            const int a = alist[i];
            const float ax = cbt[3 * a + 0];
            const float ay = cbt[3 * a + 1];
            const float az = cbt[3 * a + 2];
            if (lane < 25) {
                const int cy = (int)floorf(ay);
                const int cz = (int)floorf(az);
                const int iy = cy + lane / 5 - NNB;
                const int iz = cz + lane % 5 - NNB;
                if (iy >= y0 && iy < y0 + YHALF && (unsigned)iz < BOX) {
                    const float dx = fx - ax;
                    const float dy = (float)iy - ay;
                    const float dz = (float)iz - az;
                    const float v = __expf(-(dx * dx + dy * dy + dz * dz));
                    atomicAdd(&plane[(iy - y0) * BOX + iz], v);
                }
            }
        }
    }
    __syncthreads();

    // Phase 3: single TMA 1D bulk store smem -> gmem (28.8 KB, 16B-aligned).
    if (tid == 0) {
        float* dst = out + (long long)bt * VOL + x * (BOX * BOX) + y0 * BOX;
        asm volatile("fence.proxy.async.shared::cta;" ::: "memory");
        const uint32_t src = smem_u32(plane);
        asm volatile("cp.async.bulk.global.shared::cta.bulk_group [%0], [%1], %2;"
                     :: "l"(dst), "r"(src), "r"((uint32_t)PLANE_B) : "memory");
        asm volatile("cp.async.bulk.commit_group;" ::: "memory");
        asm volatile("cp.async.bulk.wait_group.read 0;" ::: "memory");
    }
}

// ---------------------------------------------------------------------------
extern "C" void kernel_launch(void* const* d_in, const int* in_sizes, int n_in,
                              void* d_out, int out_size) {
    const float* coords    = (const float*)d_in[0];  // float32 [4,11,1536]
    const int*   num_atoms = (const int*)d_in[1];    // int32/int64 [4,11]
    float*       out       = (float*)d_out;          // float32 [4,11,120,120,120]

    fused_kernel<<<NBLOCKS, THREADS>>>(coords, num_atoms, out);
}